// round 14
// baseline (speedup 1.0000x reference)
#include <cuda_runtime.h>
#include <cuda_bf16.h>
#include <cstdint>

// Fixed problem shapes
#define H_DIM 64
#define W_DIM 176
#define D_DIM 112
#define D4    (D_DIM / 4)          // 28 float4 chunks per feature row
#define CH    (H_DIM - 1)          // 63 cell rows
#define CW    (W_DIM - 1)          // 175 cell cols
#define NCELLS (CH * CW)           // 11025
#define CELLCAP 256                // max points per cell (mean ~45, Poisson)
#define INV65535 (1.0f / 65535.0f)
#define OUT_F4 ((H_DIM * W_DIM * D_DIM) / 4)   // 315392 float4 in output

// Scratch (device globals; zero-initialized at load; g_counts self-resets,
// g_bar is a monotonic epoch counter -> no per-launch reset needed anywhere)
__device__ int      g_counts[NCELLS];
__device__ int2     g_meta[NCELLS * CELLCAP];        // (idx, qy<<16|qx) — 8B/point
__device__ unsigned g_bar;                           // monotonic grid barrier

__device__ __forceinline__ void red_add_v4(float* addr, float a, float b, float c, float d) {
    asm volatile("red.global.add.v4.f32 [%0], {%1, %2, %3, %4};"
                 :: "l"(addr), "f"(a), "f"(b), "f"(c), "f"(d)
                 : "memory");
}

// ---------------------------------------------------------------- bin one point
__device__ __forceinline__ void bin_one(float px, float py, int i,
                                        const float4* __restrict__ feat,
                                        float* __restrict__ out)
{
    const float xf = floorf(px);
    const float yf = floorf(py);
    const int cx = min(max((int)xf, 0), CW - 1);
    const int cy = min(max((int)yf, 0), CH - 1);
    const float wx = px - xf;
    const float wy = py - yf;
    const int cell = cy * CW + cx;

    const int slot = atomicAdd(&g_counts[cell], 1);

    if (slot < CELLCAP) {
        const unsigned qx = (unsigned)__float2int_rn(wx * 65535.0f);
        const unsigned qy = (unsigned)__float2int_rn(wy * 65535.0f);
        g_meta[cell * CELLCAP + slot] = make_int2(i, (int)((qy << 16) | qx));
    } else {
        // Overflow fallback (P ~ e^-100 for this Poisson(45) input; never taken).
        const float w00 = (1.0f - wy) * (1.0f - wx);
        const float w01 = (1.0f - wy) * wx;
        const float w10 = wy * (1.0f - wx);
        const float w11 = wy * wx;
        const float4* frow = feat + (size_t)i * D4;
        float* o00 = out + ((size_t)(cy * W_DIM + cx) * D_DIM);
        float* o01 = o00 + D_DIM;
        float* o10 = o00 + (size_t)W_DIM * D_DIM;
        float* o11 = o10 + D_DIM;
        for (int k = 0; k < D4; k++) {
            const float4 f = frow[k];
            red_add_v4(o00 + k*4, w00*f.x, w00*f.y, w00*f.z, w00*f.w);
            red_add_v4(o01 + k*4, w01*f.x, w01*f.y, w01*f.z, w01*f.w);
            red_add_v4(o10 + k*4, w10*f.x, w10*f.y, w10*f.z, w10*f.w);
            red_add_v4(o11 + k*4, w11*f.x, w11*f.y, w11*f.z, w11*f.w);
        }
    }
}

// ---------------------------------------------------------------- fused persistent kernel
// Phase 1: zero output + bin all points (grid-stride, 4 pts/thread).
// Grid-wide epoch barrier (all CTAs co-resident by occupancy-sized grid).
// Phase 2: each CTA loops over cells (cell += gridDim.x), R13 cell body.
__global__ __launch_bounds__(128, 8)
void fused_kernel(const float4* __restrict__ pos2,
                  const float4* __restrict__ feat,
                  float* __restrict__ out,
                  int n)
{
    const int tid  = threadIdx.x;
    const int warp = tid >> 5;
    const int lane = tid & 31;
    const int gthread  = blockIdx.x * blockDim.x + tid;
    const int nthreads = gridDim.x * blockDim.x;

    // ---- Phase 1a: zero output (grid-stride float4 stores)
    {
        float4* o4 = reinterpret_cast<float4*>(out);
        const float4 z = make_float4(0.f, 0.f, 0.f, 0.f);
        for (int j = gthread; j < OUT_F4; j += nthreads)
            o4[j] = z;
    }

    // ---- Phase 1b: bin points, 4 per thread slot, grid-stride over quads
    const int nquads = (n + 3) >> 2;
    for (int q = gthread; q < nquads; q += nthreads) {
        const int i = q * 4;
        const float4 pa = pos2[q * 2];             // points i, i+1
        bin_one(pa.x, pa.y, i, feat, out);
        if (i + 1 < n) bin_one(pa.z, pa.w, i + 1, feat, out);
        if (i + 2 < n) {
            const float4 pb = pos2[q * 2 + 1];     // points i+2, i+3
            bin_one(pb.x, pb.y, i + 2, feat, out);
            if (i + 3 < n) bin_one(pb.z, pb.w, i + 3, feat, out);
        }
    }

    // ---- Grid barrier (monotonic epochs: no reset across graph replays)
    __syncthreads();
    if (tid == 0) {
        __threadfence();                           // publish meta/counts/zeroes
        const unsigned my = atomicAdd(&g_bar, 1u);
        const unsigned target = (my / gridDim.x + 1u) * gridDim.x;
        while ((int)(*(volatile unsigned*)&g_bar - target) < 0)
            __nanosleep(64);
    }
    __syncthreads();
    __threadfence();                               // acquire other CTAs' writes

    // ---- Phase 2: persistent cell loop
    __shared__ float4 smeta[CELLCAP];              // 4 KB (wx, wy, idx_bits, valid)
    __shared__ float4 sred[4][4][D4];              // 7 KB

    for (int cell = blockIdx.x; cell < NCELLS; cell += gridDim.x) {
        const int cnt = min(g_counts[cell], CELLCAP);
        if (cnt == 0) continue;                    // counter already 0
        const int cnt_r = (cnt + 15) & ~15;

        // Cooperative staging + unpack: coalesced 8B loads, pads zeroed.
        {
            const int base = cell * CELLCAP;
            for (int j = tid; j < cnt_r; j += 128) {
                float4 m = make_float4(0.f, 0.f, 0.f, 0.f);
                if (j < cnt) {
                    const int2 qv = g_meta[base + j];
                    m.x = (float)((unsigned)qv.y & 0xFFFFu) * INV65535;  // wx
                    m.y = (float)((unsigned)qv.y >> 16) * INV65535;      // wy
                    m.z = __int_as_float(qv.x);                           // idx bits
                    m.w = 1.0f;                                           // valid
                }
                smeta[j] = m;
            }
        }
        __syncthreads();

        const bool active = (lane < D4);
        float4 s   = {0,0,0,0};
        float4 sx  = {0,0,0,0};
        float4 sy  = {0,0,0,0};
        float4 sxy = {0,0,0,0};

        for (int j = warp; j < cnt_r; j += 16) {
            const float4 m0 = smeta[j];
            const float4 m1 = smeta[j + 4];
            const float4 m2 = smeta[j + 8];
            const float4 m3 = smeta[j + 12];
            const int i0 = __float_as_int(m0.z);
            const int i1 = __float_as_int(m1.z);
            const int i2 = __float_as_int(m2.z);
            const int i3 = __float_as_int(m3.z);
            float4 f0 = {0,0,0,0}, f1 = {0,0,0,0}, f2 = {0,0,0,0}, f3 = {0,0,0,0};
            if (active) {
                f0 = feat[(size_t)i0 * D4 + lane];
                f1 = feat[(size_t)i1 * D4 + lane];
                f2 = feat[(size_t)i2 * D4 + lane];
                f3 = feat[(size_t)i3 * D4 + lane];
            }
            {
                const float pxy = m0.x * m0.y;
                s.x   += m0.w * f0.x; s.y   += m0.w * f0.y; s.z   += m0.w * f0.z; s.w   += m0.w * f0.w;
                sx.x  += m0.x * f0.x; sx.y  += m0.x * f0.y; sx.z  += m0.x * f0.z; sx.w  += m0.x * f0.w;
                sy.x  += m0.y * f0.x; sy.y  += m0.y * f0.y; sy.z  += m0.y * f0.z; sy.w  += m0.y * f0.w;
                sxy.x += pxy  * f0.x; sxy.y += pxy  * f0.y; sxy.z += pxy  * f0.z; sxy.w += pxy  * f0.w;
            }
            {
                const float pxy = m1.x * m1.y;
                s.x   += m1.w * f1.x; s.y   += m1.w * f1.y; s.z   += m1.w * f1.z; s.w   += m1.w * f1.w;
                sx.x  += m1.x * f1.x; sx.y  += m1.x * f1.y; sx.z  += m1.x * f1.z; sx.w  += m1.x * f1.w;
                sy.x  += m1.y * f1.x; sy.y  += m1.y * f1.y; sy.z  += m1.y * f1.z; sy.w  += m1.y * f1.w;
                sxy.x += pxy  * f1.x; sxy.y += pxy  * f1.y; sxy.z += pxy  * f1.z; sxy.w += pxy  * f1.w;
            }
            {
                const float pxy = m2.x * m2.y;
                s.x   += m2.w * f2.x; s.y   += m2.w * f2.y; s.z   += m2.w * f2.z; s.w   += m2.w * f2.w;
                sx.x  += m2.x * f2.x; sx.y  += m2.x * f2.y; sx.z  += m2.x * f2.z; sx.w  += m2.x * f2.w;
                sy.x  += m2.y * f2.x; sy.y  += m2.y * f2.y; sy.z  += m2.y * f2.z; sy.w  += m2.y * f2.w;
                sxy.x += pxy  * f2.x; sxy.y += pxy  * f2.y; sxy.z += pxy  * f2.z; sxy.w += pxy  * f2.w;
            }
            {
                const float pxy = m3.x * m3.y;
                s.x   += m3.w * f3.x; s.y   += m3.w * f3.y; s.z   += m3.w * f3.z; s.w   += m3.w * f3.w;
                sx.x  += m3.x * f3.x; sx.y  += m3.x * f3.y; sx.z  += m3.x * f3.z; sx.w  += m3.x * f3.w;
                sy.x  += m3.y * f3.x; sy.y  += m3.y * f3.y; sy.z  += m3.y * f3.z; sy.w  += m3.y * f3.w;
                sxy.x += pxy  * f3.x; sxy.y += pxy  * f3.y; sxy.z += pxy  * f3.z; sxy.w += pxy  * f3.w;
            }
        }

        // Basis -> corner conversion, cross-warp reduce.
        if (active) {
            float4 a00, a01, a10, a11;
            a11.x = sxy.x;                     a11.y = sxy.y;                     a11.z = sxy.z;                     a11.w = sxy.w;
            a01.x = sx.x - sxy.x;              a01.y = sx.y - sxy.y;              a01.z = sx.z - sxy.z;              a01.w = sx.w - sxy.w;
            a10.x = sy.x - sxy.x;              a10.y = sy.y - sxy.y;              a10.z = sy.z - sxy.z;              a10.w = sy.w - sxy.w;
            a00.x = s.x - sx.x - sy.x + sxy.x; a00.y = s.y - sx.y - sy.y + sxy.y;
            a00.z = s.z - sx.z - sy.z + sxy.z; a00.w = s.w - sx.w - sy.w + sxy.w;
            sred[warp][0][lane] = a00;
            sred[warp][1][lane] = a01;
            sred[warp][2][lane] = a10;
            sred[warp][3][lane] = a11;
        }
        __syncthreads();

        // Self-reset counter for next replay.
        if (tid == 0) g_counts[cell] = 0;

        // 112 threads: corner t/28, chunk t%28. One RED.v4 each.
        if (tid < 4 * D4) {
            const int c = tid / D4;
            const int k = tid - c * D4;
            const float4 v0 = sred[0][c][k], v1 = sred[1][c][k];
            const float4 v2 = sred[2][c][k], v3 = sred[3][c][k];
            const float vx = v0.x + v1.x + v2.x + v3.x;
            const float vy = v0.y + v1.y + v2.y + v3.y;
            const float vz = v0.z + v1.z + v2.z + v3.z;
            const float vw = v0.w + v1.w + v2.w + v3.w;
            const int cy = cell / CW;
            const int cx = cell - cy * CW;
            const int dy = c >> 1, dx = c & 1;
            float* addr = out + ((size_t)((cy + dy) * W_DIM + (cx + dx)) * D_DIM + k * 4);
            red_add_v4(addr, vx, vy, vz, vw);
        }
        __syncthreads();                       // smeta/sred safe to overwrite next cell
    }
}

// ---------------------------------------------------------------- launch
extern "C" void kernel_launch(void* const* d_in, const int* in_sizes, int n_in,
                              void* d_out, int out_size)
{
    const float4* pos2 = (const float4*)d_in[0];     // (N/2, 4): two points per element
    const float4* feat = (const float4*)d_in[1];
    float* out = (float*)d_out;
    const int n = in_sizes[0] / 2;

    // Size grid for guaranteed full residency (deadlock-free barrier).
    int dev = 0;
    cudaGetDevice(&dev);
    int nsm = 148;
    cudaDeviceGetAttribute(&nsm, cudaDevAttrMultiProcessorCount, dev);
    int occ = 1;
    cudaOccupancyMaxActiveBlocksPerMultiprocessor(&occ, fused_kernel, 128, 0);
    int grid = nsm * occ;
    if (grid > NCELLS) grid = NCELLS;

    fused_kernel<<<grid, 128>>>(pos2, feat, out, n);
}

// round 15
// speedup vs baseline: 1.1758x; 1.1758x over previous
#include <cuda_runtime.h>
#include <cuda_bf16.h>
#include <cstdint>

// Fixed problem shapes
#define H_DIM 64
#define W_DIM 176
#define D_DIM 112
#define D4    (D_DIM / 4)          // 28 float4 chunks per feature row
#define CH    (H_DIM - 1)          // 63 cell rows
#define CW    (W_DIM - 1)          // 175 cell cols
#define NCELLS (CH * CW)           // 11025
#define CELLCAP 256                // max points per cell (mean ~45, Poisson)
#define INV65535 (1.0f / 65535.0f)
#define OUT_F4 ((H_DIM * W_DIM * D_DIM) / 4)   // 315392 float4 in output

// Scratch (device globals; zero-initialized at load; cell_kernel self-resets
// g_counts so no per-launch memset is needed)
__device__ int  g_counts[NCELLS];
__device__ int2 g_meta[NCELLS * CELLCAP];            // (idx, qy<<16|qx) — 8B/point

__device__ __forceinline__ void red_add_v4(float* addr, float a, float b, float c, float d) {
    asm volatile("red.global.add.v4.f32 [%0], {%1, %2, %3, %4};"
                 :: "l"(addr), "f"(a), "f"(b), "f"(c), "f"(d)
                 : "memory");
}

// ---------------------------------------------------------------- pass 1: zero-out + fused bin (4 pts/thread)
__device__ __forceinline__ void bin_one(float px, float py, int i,
                                        const float4* __restrict__ feat,
                                        float* __restrict__ out)
{
    const float xf = floorf(px);
    const float yf = floorf(py);
    const int cx = min(max((int)xf, 0), CW - 1);
    const int cy = min(max((int)yf, 0), CH - 1);
    const float wx = px - xf;
    const float wy = py - yf;
    const int cell = cy * CW + cx;

    const int slot = atomicAdd(&g_counts[cell], 1);

    if (slot < CELLCAP) {
        const unsigned qx = (unsigned)__float2int_rn(wx * 65535.0f);
        const unsigned qy = (unsigned)__float2int_rn(wy * 65535.0f);
        g_meta[cell * CELLCAP + slot] = make_int2(i, (int)((qy << 16) | qx));
    } else {
        // Overflow fallback (P ~ e^-100 for this Poisson(45) input; never taken).
        const float w00 = (1.0f - wy) * (1.0f - wx);
        const float w01 = (1.0f - wy) * wx;
        const float w10 = wy * (1.0f - wx);
        const float w11 = wy * wx;
        const float4* frow = feat + (size_t)i * D4;
        float* o00 = out + ((size_t)(cy * W_DIM + cx) * D_DIM);
        float* o01 = o00 + D_DIM;
        float* o10 = o00 + (size_t)W_DIM * D_DIM;
        float* o11 = o10 + D_DIM;
        for (int k = 0; k < D4; k++) {
            const float4 f = __ldcs(frow + k);
            red_add_v4(o00 + k*4, w00*f.x, w00*f.y, w00*f.z, w00*f.w);
            red_add_v4(o01 + k*4, w01*f.x, w01*f.y, w01*f.z, w01*f.w);
            red_add_v4(o10 + k*4, w10*f.x, w10*f.y, w10*f.z, w10*f.w);
            red_add_v4(o11 + k*4, w11*f.x, w11*f.y, w11*f.z, w11*f.w);
        }
    }
}

__global__ __launch_bounds__(256)
void bin_kernel(const float4* __restrict__ pos2,   // pos viewed as pairs of points
                const float4* __restrict__ feat,
                float* __restrict__ out,
                int n, int nthreads)
{
    const int t = blockIdx.x * blockDim.x + threadIdx.x;

    // Prologue: grid-stride zero of the output (replaces the memset node).
    {
        float4* o4 = reinterpret_cast<float4*>(out);
        const float4 z = make_float4(0.f, 0.f, 0.f, 0.f);
        for (int j = t; j < OUT_F4; j += nthreads)
            o4[j] = z;
    }

    // 4 points per thread: two adjacent float4 loads, then 4 independent
    // atomic->store chains overlap the 318-cyc ATOMG latency.
    const int i = t * 4;
    if (i >= n) return;

    const float4 pa = pos2[t * 2];             // points i, i+1
    bin_one(pa.x, pa.y, i, feat, out);
    if (i + 1 < n) bin_one(pa.z, pa.w, i + 1, feat, out);
    if (i + 2 < n) {
        const float4 pb = pos2[t * 2 + 1];     // points i+2, i+3
        bin_one(pb.x, pb.y, i + 2, feat, out);
        if (i + 3 < n) bin_one(pb.z, pb.w, i + 3, feat, out);
    }
}

// ---------------------------------------------------------------- pass 2: CTA-per-cell gather
// R13 structure; feature + meta loads use __ldcs (evict-first streaming) so
// the 224MB read-once feature stream doesn't evict the L2-resident output
// surface that red.global reductions operate on.
__global__ __launch_bounds__(128, 8)
void cell_kernel(const float4* __restrict__ feat,
                 float* __restrict__ out)
{
    const int cell = blockIdx.x;
    const int warp = threadIdx.x >> 5;
    const int lane = threadIdx.x & 31;
    const int tid  = threadIdx.x;

    const int cnt = min(g_counts[cell], CELLCAP);
    if (cnt == 0) return;                      // counter already 0 -> nothing to reset
    const int cnt_r = (cnt + 15) & ~15;        // multiple of 16 -> equal iters per warp

    __shared__ float4 smeta[CELLCAP];          // 4 KB (unpacked: wx, wy, idx_bits, valid)
    __shared__ float4 sred[4][4][D4];          // 7 KB

    // Cooperative staging + unpack: coalesced 8B streaming loads, pads zeroed.
    {
        const int base = cell * CELLCAP;
        for (int j = tid; j < cnt_r; j += 128) {
            float4 m = make_float4(0.f, 0.f, 0.f, 0.f);
            if (j < cnt) {
                const int2 q = __ldcs(&g_meta[base + j]);
                m.x = (float)((unsigned)q.y & 0xFFFFu) * INV65535;   // wx
                m.y = (float)((unsigned)q.y >> 16) * INV65535;       // wy
                m.z = __int_as_float(q.x);                            // idx bits
                m.w = 1.0f;                                           // valid
            }
            smeta[j] = m;
        }
    }
    __syncthreads();

    const bool active = (lane < D4);
    float4 s   = {0,0,0,0};   // Σ valid * f
    float4 sx  = {0,0,0,0};   // Σ wx * f
    float4 sy  = {0,0,0,0};   // Σ wy * f
    float4 sxy = {0,0,0,0};   // Σ wx*wy * f

    for (int j = warp; j < cnt_r; j += 16) {
        const float4 m0 = smeta[j];
        const float4 m1 = smeta[j + 4];
        const float4 m2 = smeta[j + 8];
        const float4 m3 = smeta[j + 12];
        const int i0 = __float_as_int(m0.z);
        const int i1 = __float_as_int(m1.z);
        const int i2 = __float_as_int(m2.z);
        const int i3 = __float_as_int(m3.z);
        float4 f0 = {0,0,0,0}, f1 = {0,0,0,0}, f2 = {0,0,0,0}, f3 = {0,0,0,0};
        if (active) {
            f0 = __ldcs(&feat[(size_t)i0 * D4 + lane]);
            f1 = __ldcs(&feat[(size_t)i1 * D4 + lane]);
            f2 = __ldcs(&feat[(size_t)i2 * D4 + lane]);
            f3 = __ldcs(&feat[(size_t)i3 * D4 + lane]);
        }
        {
            const float pxy = m0.x * m0.y;
            s.x   += m0.w * f0.x; s.y   += m0.w * f0.y; s.z   += m0.w * f0.z; s.w   += m0.w * f0.w;
            sx.x  += m0.x * f0.x; sx.y  += m0.x * f0.y; sx.z  += m0.x * f0.z; sx.w  += m0.x * f0.w;
            sy.x  += m0.y * f0.x; sy.y  += m0.y * f0.y; sy.z  += m0.y * f0.z; sy.w  += m0.y * f0.w;
            sxy.x += pxy  * f0.x; sxy.y += pxy  * f0.y; sxy.z += pxy  * f0.z; sxy.w += pxy  * f0.w;
        }
        {
            const float pxy = m1.x * m1.y;
            s.x   += m1.w * f1.x; s.y   += m1.w * f1.y; s.z   += m1.w * f1.z; s.w   += m1.w * f1.w;
            sx.x  += m1.x * f1.x; sx.y  += m1.x * f1.y; sx.z  += m1.x * f1.z; sx.w  += m1.x * f1.w;
            sy.x  += m1.y * f1.x; sy.y  += m1.y * f1.y; sy.z  += m1.y * f1.z; sy.w  += m1.y * f1.w;
            sxy.x += pxy  * f1.x; sxy.y += pxy  * f1.y; sxy.z += pxy  * f1.z; sxy.w += pxy  * f1.w;
        }
        {
            const float pxy = m2.x * m2.y;
            s.x   += m2.w * f2.x; s.y   += m2.w * f2.y; s.z   += m2.w * f2.z; s.w   += m2.w * f2.w;
            sx.x  += m2.x * f2.x; sx.y  += m2.x * f2.y; sx.z  += m2.x * f2.z; sx.w  += m2.x * f2.w;
            sy.x  += m2.y * f2.x; sy.y  += m2.y * f2.y; sy.z  += m2.y * f2.z; sy.w  += m2.y * f2.w;
            sxy.x += pxy  * f2.x; sxy.y += pxy  * f2.y; sxy.z += pxy  * f2.z; sxy.w += pxy  * f2.w;
        }
        {
            const float pxy = m3.x * m3.y;
            s.x   += m3.w * f3.x; s.y   += m3.w * f3.y; s.z   += m3.w * f3.z; s.w   += m3.w * f3.w;
            sx.x  += m3.x * f3.x; sx.y  += m3.x * f3.y; sx.z  += m3.x * f3.z; sx.w  += m3.x * f3.w;
            sy.x  += m3.y * f3.x; sy.y  += m3.y * f3.y; sy.z  += m3.y * f3.z; sy.w  += m3.y * f3.w;
            sxy.x += pxy  * f3.x; sxy.y += pxy  * f3.y; sxy.z += pxy  * f3.z; sxy.w += pxy  * f3.w;
        }
    }

    // Basis -> corner conversion (per warp, in registers), then cross-warp reduce.
    if (active) {
        float4 a00, a01, a10, a11;
        a11.x = sxy.x;                     a11.y = sxy.y;                     a11.z = sxy.z;                     a11.w = sxy.w;
        a01.x = sx.x - sxy.x;              a01.y = sx.y - sxy.y;              a01.z = sx.z - sxy.z;              a01.w = sx.w - sxy.w;
        a10.x = sy.x - sxy.x;              a10.y = sy.y - sxy.y;              a10.z = sy.z - sxy.z;              a10.w = sy.w - sxy.w;
        a00.x = s.x - sx.x - sy.x + sxy.x; a00.y = s.y - sx.y - sy.y + sxy.y;
        a00.z = s.z - sx.z - sy.z + sxy.z; a00.w = s.w - sx.w - sy.w + sxy.w;
        sred[warp][0][lane] = a00;
        sred[warp][1][lane] = a01;
        sred[warp][2][lane] = a10;
        sred[warp][3][lane] = a11;
    }
    __syncthreads();

    // Self-reset counter for next replay (ordered after every thread's read of
    // g_counts by the two barriers above; each CTA touches only its own cell).
    if (tid == 0) g_counts[cell] = 0;

    // 112 threads: thread t -> corner t/28, chunk t%28. One RED.v4 each.
    if (tid < 4 * D4) {
        const int c = tid / D4;
        const int k = tid - c * D4;
        const float4 v0 = sred[0][c][k], v1 = sred[1][c][k];
        const float4 v2 = sred[2][c][k], v3 = sred[3][c][k];
        const float vx = v0.x + v1.x + v2.x + v3.x;
        const float vy = v0.y + v1.y + v2.y + v3.y;
        const float vz = v0.z + v1.z + v2.z + v3.z;
        const float vw = v0.w + v1.w + v2.w + v3.w;
        const int cy = cell / CW;
        const int cx = cell - cy * CW;
        const int dy = c >> 1, dx = c & 1;
        float* addr = out + ((size_t)((cy + dy) * W_DIM + (cx + dx)) * D_DIM + k * 4);
        red_add_v4(addr, vx, vy, vz, vw);
    }
}

// ---------------------------------------------------------------- launch
extern "C" void kernel_launch(void* const* d_in, const int* in_sizes, int n_in,
                              void* d_out, int out_size)
{
    const float4* pos2 = (const float4*)d_in[0];     // (N/2, 4): two points per element
    const float4* feat = (const float4*)d_in[1];
    float* out = (float*)d_out;
    const int n = in_sizes[0] / 2;

    const int nt = (n + 3) / 4;                      // threads (4 pts each)
    const int nblk = (nt + 255) / 256;
    bin_kernel<<<nblk, 256>>>(pos2, feat, out, n, nblk * 256);
    cell_kernel<<<NCELLS, 128>>>(feat, out);
}